// round 3
// baseline (speedup 1.0000x reference)
#include <cuda_runtime.h>

#define NB     4
#define DIMC   128
#define NSEQ   16384
#define BNTOK  65536
#define LC     64
#define NCH    256

// ---------------- scratch ----------------
__device__ float g_u [2u*BNTOK*128];
__device__ float g_z [2u*BNTOK*128];
__device__ float g_uc[2u*BNTOK*128];
__device__ float g_dt[2u*BNTOK*128];
__device__ float g_ys[2u*BNTOK*128];
__device__ float g_B [2u*BNTOK*8];
__device__ float g_C [2u*BNTOK*8];
__device__ float g_P [2u*4*NCH*128*8];
__device__ float g_Q [2u*4*NCH*128*8];
__device__ float g_H [2u*4*NCH*128*8];
__device__ float g_Weff[2u*128*128];
__device__ float g_beff[128];

// ---------------- f32x2 helpers ----------------
__device__ __forceinline__ unsigned long long fma2(unsigned long long a, unsigned long long b,
                                                   unsigned long long c) {
    unsigned long long d;
    asm("fma.rn.f32x2 %0, %1, %2, %3;" : "=l"(d) : "l"(a), "l"(b), "l"(c));
    return d;
}
__device__ __forceinline__ unsigned long long pack2(float x, float y) {
    unsigned long long r;
    asm("mov.b64 %0, {%1, %2};" : "=l"(r) : "f"(x), "f"(y));
    return r;
}
__device__ __forceinline__ float2 unpk2(unsigned long long v) {
    float2 r;
    asm("mov.b64 {%0, %1}, %2;" : "=f"(r.x), "=f"(r.y) : "l"(v));
    return r;
}
__device__ __forceinline__ float sigmoidf_fast(float x) { return 1.0f / (1.0f + __expf(-x)); }
__device__ __forceinline__ float softplusf(float x) { return (x > 15.0f) ? x : log1pf(__expf(x)); }

// ---------------- shared GEMM micro-kernel ----------------
// xs: [128][68] feature-major (64 tokens), Ws: [128][128] row-major.
__device__ __forceinline__ void gemm_tile(const float* __restrict__ xs,
                                          const float* __restrict__ Ws,
                                          int t0, int j0,
                                          unsigned long long acc[4][4]) {
#pragma unroll 4
    for (int d = 0; d < 128; ++d) {
        float4 xv = *(const float4*)(xs + d * 68 + t0);
        unsigned long long x0 = pack2(xv.x, xv.x);
        unsigned long long x1 = pack2(xv.y, xv.y);
        unsigned long long x2 = pack2(xv.z, xv.z);
        unsigned long long x3 = pack2(xv.w, xv.w);
        const unsigned long long* wp = (const unsigned long long*)(Ws + d * 128 + j0);
        unsigned long long w0 = wp[0], w1 = wp[1], w2 = wp[2], w3 = wp[3];
        acc[0][0] = fma2(x0, w0, acc[0][0]); acc[0][1] = fma2(x0, w1, acc[0][1]);
        acc[0][2] = fma2(x0, w2, acc[0][2]); acc[0][3] = fma2(x0, w3, acc[0][3]);
        acc[1][0] = fma2(x1, w0, acc[1][0]); acc[1][1] = fma2(x1, w1, acc[1][1]);
        acc[1][2] = fma2(x1, w2, acc[1][2]); acc[1][3] = fma2(x1, w3, acc[1][3]);
        acc[2][0] = fma2(x2, w0, acc[2][0]); acc[2][1] = fma2(x2, w1, acc[2][1]);
        acc[2][2] = fma2(x2, w2, acc[2][2]); acc[2][3] = fma2(x2, w3, acc[2][3]);
        acc[3][0] = fma2(x3, w0, acc[3][0]); acc[3][1] = fma2(x3, w1, acc[3][1]);
        acc[3][2] = fma2(x3, w2, acc[3][2]); acc[3][3] = fma2(x3, w3, acc[3][3]);
    }
}

// ---------------- Kernel 0: Weff precompute ----------------
__global__ void weff_kernel(const float* __restrict__ Wm, const float* __restrict__ bm,
                            const float* __restrict__ Wout, const float* __restrict__ bout) {
    int j = threadIdx.x, r = blockIdx.x, i = blockIdx.y;
    float acc = 0.f;
    for (int k = 0; k < 128; ++k) acc += Wm[i * 16384 + r * 128 + k] * Wout[k * 128 + j];
    g_Weff[i * 16384 + r * 128 + j] = 0.5f * acc;
    if (r == 0 && i == 0) {
        float b = bout[j];
        for (int k = 0; k < 128; ++k) b += 0.5f * (bm[k] + bm[128 + k]) * Wout[k * 128 + j];
        g_beff[j] = b;
    }
}

// ---------------- Kernel 1: LN + input GEMMs ----------------
// grid (1024, 4), block 256, dyn smem 100352 B
extern "C" __global__ void __launch_bounds__(256) ln_gemm_kernel(
    const float* __restrict__ front, const float* __restrict__ back,
    const float* __restrict__ ln0w, const float* __restrict__ ln0b,
    const float* __restrict__ ln1w, const float* __restrict__ ln1b,
    const float* __restrict__ Wx, const float* __restrict__ Wz) {
    extern __shared__ float sm[];
    float* xs = sm;              // 128 x 68
    float* Ws = sm + 128 * 68;   // 128 x 128
    __shared__ float s_red[8][64];
    __shared__ float s_mean[64], s_rstd[64];
    __shared__ float s_lnw[128], s_lnb[128];

    int c = blockIdx.y;
    int dir = c >> 1;
    const float* src = (c == 0 || c == 3) ? front : back;
    const float* lw = (c & 1) ? ln1w + dir * 128 : ln0w + dir * 128;
    const float* lb = (c & 1) ? ln1b + dir * 128 : ln0b + dir * 128;
    const float* W  = ((c & 1) ? Wz : Wx) + dir * 128 * 128;
    float* out = ((c & 1) ? g_z : g_u) + (size_t)dir * BNTOK * 128;

    int g0 = blockIdx.x * 64;
    int b  = g0 >> 14;
    int n0 = g0 & (NSEQ - 1);
    const float* sbase = src + (size_t)b * 128 * NSEQ + n0;
    int tid = threadIdx.x;

#pragma unroll
    for (int it = 0; it < 8; ++it) {
        int idx = tid + it * 256;
        int d = idx >> 4, v = idx & 15;
        *(float4*)(xs + d * 68 + v * 4) = *(const float4*)(sbase + (size_t)d * NSEQ + v * 4);
    }
    if (tid < 128) { s_lnw[tid] = lw[tid]; s_lnb[tid] = lb[tid]; }
#pragma unroll
    for (int it = 0; it < 16; ++it) {
        int idx = tid + it * 256;
        *(float4*)(Ws + idx * 4) = *(const float4*)(W + idx * 4);
    }
    __syncthreads();

    {
        int t = tid & 63, part = tid >> 6;
        float s = 0.f, s2 = 0.f;
        for (int d = part * 32; d < part * 32 + 32; ++d) {
            float x = xs[d * 68 + t];
            s += x; s2 += x * x;
        }
        s_red[part][t] = s;
        s_red[part + 4][t] = s2;
    }
    __syncthreads();
    if (tid < 64) {
        float m = (s_red[0][tid] + s_red[1][tid] + s_red[2][tid] + s_red[3][tid]) * (1.f / 128.f);
        float q = (s_red[4][tid] + s_red[5][tid] + s_red[6][tid] + s_red[7][tid]) * (1.f / 128.f);
        s_mean[tid] = m;
        s_rstd[tid] = rsqrtf(q - m * m + 1e-5f);
    }
    __syncthreads();
#pragma unroll
    for (int it = 0; it < 8; ++it) {
        int idx = tid + it * 256;
        int d = idx >> 4, v = idx & 15, t = v * 4;
        float4 x = *(float4*)(xs + d * 68 + v * 4);
        float w = s_lnw[d], bb = s_lnb[d];
        x.x = (x.x - s_mean[t + 0]) * s_rstd[t + 0] * w + bb;
        x.y = (x.y - s_mean[t + 1]) * s_rstd[t + 1] * w + bb;
        x.z = (x.z - s_mean[t + 2]) * s_rstd[t + 2] * w + bb;
        x.w = (x.w - s_mean[t + 3]) * s_rstd[t + 3] * w + bb;
        *(float4*)(xs + d * 68 + v * 4) = x;
    }
    __syncthreads();

    int jt = tid & 15, tt = tid >> 4;
    int j0 = jt * 8, t0 = tt * 4;
    unsigned long long acc[4][4];
#pragma unroll
    for (int t = 0; t < 4; ++t)
#pragma unroll
        for (int p = 0; p < 4; ++p) acc[t][p] = 0ull;

    gemm_tile(xs, Ws, t0, j0, acc);

#pragma unroll
    for (int t = 0; t < 4; ++t) {
        float2 a0 = unpk2(acc[t][0]), a1 = unpk2(acc[t][1]);
        float2 a2 = unpk2(acc[t][2]), a3 = unpk2(acc[t][3]);
        float4 o0 = {a0.x, a0.y, a1.x, a1.y};
        float4 o1 = {a2.x, a2.y, a3.x, a3.y};
        float* op = out + (size_t)(g0 + t0 + t) * 128 + j0;
        *(float4*)op = o0;
        *(float4*)(op + 4) = o1;
    }
}

// ---------------- Kernel 2: causal depthwise conv + SiLU ----------------
extern "C" __global__ void __launch_bounds__(256) conv_silu_kernel(
    const float* __restrict__ conv_w, const float* __restrict__ conv_b) {
    unsigned idx = blockIdx.x * 256u + threadIdx.x;
    int d = idx & 127;
    int n = (idx >> 7) & (NSEQ - 1);
    int i = idx >> 23;
    const float* w = conv_w + i * 512 + d * 4;
    float acc = conv_b[i * 128 + d];
#pragma unroll
    for (int k = 0; k < 4; ++k) {
        if (n + k >= 3) acc += w[k] * g_u[idx + (unsigned)((k - 3) * 128)];
    }
    g_uc[idx] = acc * sigmoidf_fast(acc);
}

// ---------------- Kernel 3: x_dbl projection -> dt/B/C ----------------
// grid (2048, 2), block 128
extern "C" __global__ void __launch_bounds__(128) proj_kernel(
    const float* __restrict__ Wxproj, const float* __restrict__ Wdt,
    const float* __restrict__ bdt) {
    __shared__ float ucs[32 * 132];
    __shared__ float wxp[128 * 24];
    __shared__ float xd[32 * 25];
    __shared__ float wdts[8 * 128];
    __shared__ float bdts[128];

    int i = blockIdx.y;
    int g0 = blockIdx.x * 32;
    int tid = threadIdx.x;

#pragma unroll
    for (int k = 0; k < 8; ++k) {
        int idx = tid + k * 128;
        int t = idx >> 5, dv = idx & 31;
        *(float4*)(ucs + t * 132 + dv * 4) =
            *(const float4*)(g_uc + ((size_t)i * BNTOK + g0 + t) * 128 + dv * 4);
    }
#pragma unroll
    for (int k = 0; k < 24; ++k) wxp[tid + k * 128] = Wxproj[i * 3072 + tid + k * 128];
#pragma unroll
    for (int k = 0; k < 8; ++k) wdts[tid + k * 128] = Wdt[i * 1024 + tid + k * 128];
    bdts[tid] = bdt[i * 128 + tid];
    __syncthreads();

    {
        int t = tid >> 2, p = tid & 3, j0 = p * 6;
        float a[6];
#pragma unroll
        for (int q = 0; q < 6; ++q) a[q] = 0.f;
        for (int d = 0; d < 128; ++d) {
            float x = ucs[t * 132 + d];
#pragma unroll
            for (int q = 0; q < 6; ++q) a[q] += x * wxp[d * 24 + j0 + q];
        }
#pragma unroll
        for (int q = 0; q < 6; ++q) xd[t * 25 + j0 + q] = a[q];
    }
    __syncthreads();

    {
        int dd = tid;
        for (int t = 0; t < 32; ++t) {
            float acc = bdts[dd];
#pragma unroll
            for (int r = 0; r < 8; ++r) acc += xd[t * 25 + r] * wdts[r * 128 + dd];
            g_dt[((size_t)i * BNTOK + g0 + t) * 128 + dd] = softplusf(acc);
        }
    }
    for (int idx = tid; idx < 512; idx += 128) {
        int t = idx >> 4, q = idx & 15;
        float v = xd[t * 25 + 8 + q];
        size_t gg = ((size_t)i * BNTOK + g0 + t) * 8;
        if (q < 8) g_B[gg + q] = v;
        else       g_C[gg + q - 8] = v;
    }
}

// ---------------- Kernel 4a: per-chunk local scan ----------------
// grid 2048 (= 2*4*256), block 128
extern "C" __global__ void __launch_bounds__(128) scan_a_kernel(const float* __restrict__ A_log) {
    __shared__ float Bs[LC * 8];
    int bx = blockIdx.x;
    int c = bx & (NCH - 1), b = (bx >> 8) & 3, i = bx >> 10;
    int d = threadIdx.x;
    float a[8];
#pragma unroll
    for (int s = 0; s < 8; ++s) a[s] = -__expf(A_log[i * 1024 + d * 8 + s]);

    size_t gtok0 = (size_t)i * BNTOK + b * NSEQ + c * LC;
    for (int k = d; k < LC * 8; k += 128) Bs[k] = g_B[gtok0 * 8 + k];
    __syncthreads();

    float P[8], h[8];
#pragma unroll
    for (int s = 0; s < 8; ++s) { P[s] = 1.f; h[s] = 0.f; }
    const float* dtp = g_dt + gtok0 * 128 + d;
    const float* ucp = g_uc + gtok0 * 128 + d;
#pragma unroll 2
    for (int t = 0; t < LC; ++t) {
        float dtv = dtp[t * 128], ucv = ucp[t * 128];
        float du = dtv * ucv;
#pragma unroll
        for (int s = 0; s < 8; ++s) {
            float dA = __expf(dtv * a[s]);
            P[s] *= dA;
            h[s] = dA * h[s] + du * Bs[t * 8 + s];
        }
    }
    size_t o = ((size_t)((i * 4 + b) * NCH + c)) * 1024 + d * 8;
    *(float4*)(g_P + o)     = make_float4(P[0], P[1], P[2], P[3]);
    *(float4*)(g_P + o + 4) = make_float4(P[4], P[5], P[6], P[7]);
    *(float4*)(g_Q + o)     = make_float4(h[0], h[1], h[2], h[3]);
    *(float4*)(g_Q + o + 4) = make_float4(h[4], h[5], h[6], h[7]);
}

// ---------------- Kernel 4b: chunk combine ----------------
// grid 32, block 256  (8192 = 2*4*128*8 threads)
extern "C" __global__ void __launch_bounds__(256) scan_b_kernel() {
    int idx = blockIdx.x * 256 + threadIdx.x;
    int ib = idx >> 10, ds = idx & 1023;
    size_t base = (size_t)ib * NCH * 1024 + ds;
    float h = 0.f;
    for (int c0 = 0; c0 < NCH; c0 += 8) {
        float P8[8], Q8[8];
#pragma unroll
        for (int k = 0; k < 8; ++k) {
            size_t o = base + (size_t)(c0 + k) * 1024;
            P8[k] = g_P[o]; Q8[k] = g_Q[o];
        }
#pragma unroll
        for (int k = 0; k < 8; ++k) {
            size_t o = base + (size_t)(c0 + k) * 1024;
            g_H[o] = h;
            h = P8[k] * h + Q8[k];
        }
    }
}

// ---------------- Kernel 4c: replay + fused epilogue ----------------
// grid 2048, block 128
extern "C" __global__ void __launch_bounds__(128) scan_c_kernel(
    const float* __restrict__ A_log, const float* __restrict__ Dp) {
    __shared__ float Bs[LC * 8];
    __shared__ float Cs[LC * 8];
    int bx = blockIdx.x;
    int c = bx & (NCH - 1), b = (bx >> 8) & 3, i = bx >> 10;
    int d = threadIdx.x;
    float a[8];
#pragma unroll
    for (int s = 0; s < 8; ++s) a[s] = -__expf(A_log[i * 1024 + d * 8 + s]);
    float dp = Dp[i * 128 + d];

    size_t gtok0 = (size_t)i * BNTOK + b * NSEQ + c * LC;
    for (int k = d; k < LC * 8; k += 128) {
        Bs[k] = g_B[gtok0 * 8 + k];
        Cs[k] = g_C[gtok0 * 8 + k];
    }
    __syncthreads();

    size_t o = ((size_t)((i * 4 + b) * NCH + c)) * 1024 + d * 8;
    float h[8];
    float4 h0 = *(const float4*)(g_H + o);
    float4 h1 = *(const float4*)(g_H + o + 4);
    h[0] = h0.x; h[1] = h0.y; h[2] = h0.z; h[3] = h0.w;
    h[4] = h1.x; h[5] = h1.y; h[6] = h1.z; h[7] = h1.w;

    const float* dtp = g_dt + gtok0 * 128 + d;
    const float* ucp = g_uc + gtok0 * 128 + d;
    const float* zp  = g_z  + gtok0 * 128 + d;
    float* yp        = g_ys + gtok0 * 128 + d;
#pragma unroll 2
    for (int t = 0; t < LC; ++t) {
        float dtv = dtp[t * 128], ucv = ucp[t * 128], zv = zp[t * 128];
        float du = dtv * ucv;
        float y = 0.f;
#pragma unroll
        for (int s = 0; s < 8; ++s) {
            float dA = __expf(dtv * a[s]);
            h[s] = dA * h[s] + du * Bs[t * 8 + s];
            y += h[s] * Cs[t * 8 + s];
        }
        float yy = y + dp * ucv;
        yp[t * 128] = yy * (zv * sigmoidf_fast(zv));
    }
}

// ---------------- Kernel 5: output GEMM (3 accumulated matmuls) ----------------
// grid 1024, block 256, dyn smem 100352 B
extern "C" __global__ void __launch_bounds__(256) out_gemm_kernel(
    const float* __restrict__ front, const float* __restrict__ back,
    const float* __restrict__ Wout, float* __restrict__ outp) {
    extern __shared__ float sm[];
    float* xs = sm;
    float* Ws = sm + 128 * 68;

    int g0 = blockIdx.x * 64;
    int b  = g0 >> 14;
    int n0 = g0 & (NSEQ - 1);
    int tid = threadIdx.x;
    int jt = tid & 15, tt = tid >> 4;
    int j0 = jt * 8, t0 = tt * 4;

    unsigned long long acc[4][4];
#pragma unroll
    for (int t = 0; t < 4; ++t)
#pragma unroll
        for (int p = 0; p < 4; ++p) acc[t][p] = 0ull;

    // phase 0: 0.5*(front+back) @ Wout
    {
        const float* f = front + (size_t)b * 128 * NSEQ + n0;
        const float* g = back  + (size_t)b * 128 * NSEQ + n0;
#pragma unroll
        for (int it = 0; it < 8; ++it) {
            int idx = tid + it * 256;
            int d = idx >> 4, v = idx & 15;
            float4 x = *(const float4*)(f + (size_t)d * NSEQ + v * 4);
            float4 y = *(const float4*)(g + (size_t)d * NSEQ + v * 4);
            x.x = 0.5f * (x.x + y.x); x.y = 0.5f * (x.y + y.y);
            x.z = 0.5f * (x.z + y.z); x.w = 0.5f * (x.w + y.w);
            *(float4*)(xs + d * 68 + v * 4) = x;
        }
#pragma unroll
        for (int it = 0; it < 16; ++it) {
            int idx = tid + it * 256;
            *(float4*)(Ws + idx * 4) = *(const float4*)(Wout + idx * 4);
        }
        __syncthreads();
        gemm_tile(xs, Ws, t0, j0, acc);
        __syncthreads();
    }

    // phases 1,2: y_i @ Weff_i
    for (int i = 0; i < 2; ++i) {
        const float* ysrc = g_ys + ((size_t)i * BNTOK + g0) * 128;
#pragma unroll
        for (int it = 0; it < 8; ++it) {
            int idx = tid + it * 256;
            int t = idx >> 5, dv = idx & 31;
            float4 v = *(const float4*)(ysrc + (size_t)t * 128 + dv * 4);
            xs[(dv * 4 + 0) * 68 + t] = v.x;
            xs[(dv * 4 + 1) * 68 + t] = v.y;
            xs[(dv * 4 + 2) * 68 + t] = v.z;
            xs[(dv * 4 + 3) * 68 + t] = v.w;
        }
#pragma unroll
        for (int it = 0; it < 16; ++it) {
            int idx = tid + it * 256;
            *(float4*)(Ws + idx * 4) = *(const float4*)(g_Weff + i * 16384 + idx * 4);
        }
        __syncthreads();
        gemm_tile(xs, Ws, t0, j0, acc);
        __syncthreads();
    }

    // store channel-major: out[(b*128 + j)*NSEQ + n]
    float* ob = outp + ((size_t)b * 128) * NSEQ + n0 + t0;
#pragma unroll
    for (int p = 0; p < 4; ++p) {
        float2 a0 = unpk2(acc[0][p]), a1 = unpk2(acc[1][p]);
        float2 a2 = unpk2(acc[2][p]), a3 = unpk2(acc[3][p]);
        int j = j0 + 2 * p;
        float be = g_beff[j], bo = g_beff[j + 1];
        float4 v0 = {a0.x + be, a1.x + be, a2.x + be, a3.x + be};
        float4 v1 = {a0.y + bo, a1.y + bo, a2.y + bo, a3.y + bo};
        *(float4*)(ob + (size_t)j * NSEQ) = v0;
        *(float4*)(ob + (size_t)(j + 1) * NSEQ) = v1;
    }
}

// ---------------- launch ----------------
extern "C" void kernel_launch(void* const* d_in, const int* in_sizes, int n_in,
                              void* d_out, int out_size) {
    const float* front  = (const float*)d_in[0];
    const float* back   = (const float*)d_in[1];
    const float* ln0w   = (const float*)d_in[2];
    const float* ln0b   = (const float*)d_in[3];
    const float* ln1w   = (const float*)d_in[4];
    const float* ln1b   = (const float*)d_in[5];
    const float* Wx     = (const float*)d_in[6];
    const float* Wz     = (const float*)d_in[7];
    const float* conv_w = (const float*)d_in[8];
    const float* conv_b = (const float*)d_in[9];
    const float* Wxproj = (const float*)d_in[10];
    const float* Wdt    = (const float*)d_in[11];
    const float* bdt    = (const float*)d_in[12];
    const float* A_log  = (const float*)d_in[13];
    const float* Dp     = (const float*)d_in[14];
    const float* Wout_m = (const float*)d_in[15];
    const float* bout_m = (const float*)d_in[16];
    const float* Wout   = (const float*)d_in[17];
    const float* bout   = (const float*)d_in[18];
    float* out = (float*)d_out;

    const int SMEM1 = (128 * 68 + 128 * 128) * 4;
    cudaFuncSetAttribute(ln_gemm_kernel, cudaFuncAttributeMaxDynamicSharedMemorySize, SMEM1);
    cudaFuncSetAttribute(out_gemm_kernel, cudaFuncAttributeMaxDynamicSharedMemorySize, SMEM1);

    weff_kernel<<<dim3(128, 2), 128>>>(Wout_m, bout_m, Wout, bout);
    ln_gemm_kernel<<<dim3(1024, 4), 256, SMEM1>>>(front, back, ln0w, ln0b, ln1w, ln1b, Wx, Wz);
    conv_silu_kernel<<<65536, 256>>>(conv_w, conv_b);
    proj_kernel<<<dim3(2048, 2), 128>>>(Wxproj, Wdt, bdt);
    scan_a_kernel<<<2048, 128>>>(A_log);
    scan_b_kernel<<<32, 256>>>();
    scan_c_kernel<<<2048, 128>>>(A_log, Dp);
    out_gemm_kernel<<<1024, 256, SMEM1>>>(front, back, Wout, out);
}

// round 5
// speedup vs baseline: 1.3952x; 1.3952x over previous
#include <cuda_runtime.h>
#include <cuda_bf16.h>
#include <cstdint>

#define NSEQ   16384
#define BNTOK  65536
#define LC     64
#define NCH    256
#define NTILE  512
#define SASTR  272   // smem row stride in bytes (136 bf16)

// A planes: 0=xhat_ff 1=xhat_bf 2=m 3=y0 4=y1 ; [hi/lo] ; row-major [token][128]
__device__ __nv_bfloat16 g_Abf[5][2][(size_t)BNTOK * 128];
// W planes transposed [j][k]: 0..3 = u0,z0,u1,z1 ; 4=Wout ; 5=Weff0 ; 6=Weff1
__device__ __nv_bfloat16 g_Wtb[7][2][16384];
__device__ float g_biasv[640];

__device__ float g_u [2u*BNTOK*128];
__device__ float g_z [2u*BNTOK*128];
__device__ float g_uc[2u*BNTOK*128];
__device__ float g_dt[2u*BNTOK*128];
__device__ float g_B [2u*BNTOK*8];
__device__ float g_C [2u*BNTOK*8];
__device__ float g_P [2u*4*NCH*128*8];
__device__ float g_Q [2u*4*NCH*128*8];
__device__ float g_H [2u*4*NCH*128*8];

__device__ __forceinline__ float sigmoidf_fast(float x) { return 1.0f / (1.0f + __expf(-x)); }
__device__ __forceinline__ float softplusf(float x) { return (x > 15.0f) ? x : log1pf(__expf(x)); }
__device__ __forceinline__ uint32_t su32(const void* p) { return (uint32_t)__cvta_generic_to_shared(p); }

__device__ __forceinline__ void splt(float a, float b, uint32_t& hi, uint32_t& lo) {
    __nv_bfloat162 h, l;
    h.x = __float2bfloat16_rn(a); h.y = __float2bfloat16_rn(b);
    l.x = __float2bfloat16_rn(a - __bfloat162float(h.x));
    l.y = __float2bfloat16_rn(b - __bfloat162float(h.y));
    hi = *(uint32_t*)&h; lo = *(uint32_t*)&l;
}
__device__ __forceinline__ void ldsm4(uint32_t addr, uint32_t r[4]) {
    asm volatile("ldmatrix.sync.aligned.m8n8.x4.shared.b16 {%0,%1,%2,%3}, [%4];"
                 : "=r"(r[0]), "=r"(r[1]), "=r"(r[2]), "=r"(r[3]) : "r"(addr));
}
__device__ __forceinline__ void mma16816(float d[4], const uint32_t a[4], const uint32_t b[2]) {
    asm volatile("mma.sync.aligned.m16n8k16.row.col.f32.bf16.bf16.f32 "
                 "{%0,%1,%2,%3},{%4,%5,%6,%7},{%8,%9},{%0,%1,%2,%3};"
                 : "+f"(d[0]), "+f"(d[1]), "+f"(d[2]), "+f"(d[3])
                 : "r"(a[0]), "r"(a[1]), "r"(a[2]), "r"(a[3]), "r"(b[0]), "r"(b[1]));
}

// stage a 128x128 bf16 plane into smem with 272B row stride
__device__ __forceinline__ void stage_plane(const __nv_bfloat16* __restrict__ g,
                                            unsigned char* s, int tid) {
#pragma unroll
    for (int it = 0; it < 8; ++it) {
        int idx = tid + it * 256;
        int r = idx >> 4, c = idx & 15;
        *(uint4*)(s + r * SASTR + c * 16) = ((const uint4*)g)[idx];
    }
}

// 3-pass (hi/lo split) 128x128x128 GEMM over staged smem: Ah@0, Al@34816, Bh@69632, Bl@104448
__device__ __forceinline__ void gemm_compute(unsigned char* smem, float acc[16][4],
                                             int warp, int lane) {
    uint32_t sb = su32(smem);
    int row = lane & 7, g = lane >> 3;
    uint32_t aoff = (uint32_t)((warp * 16 + (g & 1) * 8 + row) * SASTR + (g >> 1) * 16);
    uint32_t boff = (uint32_t)(((g >> 1) * 8 + row) * SASTR + (g & 1) * 16);
#pragma unroll
    for (int pass = 0; pass < 3; ++pass) {
        uint32_t Ab = sb + (pass == 1 ? 34816u : 0u);
        uint32_t Bb = sb + 69632u + (pass == 2 ? 34816u : 0u);
#pragma unroll
        for (int kk = 0; kk < 8; ++kk) {
            uint32_t k2 = (uint32_t)kk * 32u;
            uint32_t a[4];
            ldsm4(Ab + aoff + k2, a);
#pragma unroll
            for (int nt = 0; nt < 8; ++nt) {
                uint32_t br[4];
                ldsm4(Bb + boff + (uint32_t)(nt * 16 * SASTR) + k2, br);
                mma16816(acc[2 * nt], a, br);
                mma16816(acc[2 * nt + 1], a, br + 2);
            }
        }
    }
}

// ---------------- prep_w: transposed bf16-split weight planes + biases ----------------
extern "C" __global__ void prep_w_kernel(
    const float* __restrict__ ln0w, const float* __restrict__ ln0b,
    const float* __restrict__ ln1w, const float* __restrict__ ln1b,
    const float* __restrict__ Wx, const float* __restrict__ Wz,
    const float* __restrict__ Wm, const float* __restrict__ bm,
    const float* __restrict__ Wout, const float* __restrict__ bout) {
    int j = blockIdx.x, pl = blockIdx.y, k = threadIdx.x;
    __shared__ float red[128];
    float v = 0.f, bc = 0.f;
    if (pl < 4) {
        int dir = pl >> 1;
        const float* W  = ((pl & 1) ? Wz : Wx) + dir * 16384;
        const float* lw = ((pl & 1) ? ln1w : ln0w) + dir * 128;
        const float* lb = ((pl & 1) ? ln1b : ln0b) + dir * 128;
        float wv = W[k * 128 + j];
        v = lw[k] * wv; bc = lb[k] * wv;
    } else if (pl == 4) {
        float wv = Wout[k * 128 + j];
        v = wv; bc = 0.5f * (bm[k] + bm[128 + k]) * wv;
    } else {
        int i = pl - 5;
        float acc = 0.f;
        for (int t = 0; t < 128; ++t) acc += Wm[i * 16384 + k * 128 + t] * Wout[t * 128 + j];
        v = 0.5f * acc;
    }
    __nv_bfloat16 h = __float2bfloat16_rn(v);
    g_Wtb[pl][0][j * 128 + k] = h;
    g_Wtb[pl][1][j * 128 + k] = __float2bfloat16_rn(v - __bfloat162float(h));
    if (pl < 5) {
        red[k] = bc; __syncthreads();
        if (k == 0) {
            float s = 0.f;
            for (int t = 0; t < 128; ++t) s += red[t];
            if (pl < 4) g_biasv[pl * 128 + j] = s;
            else        g_biasv[512 + j] = s + bout[j];
        }
    }
}

// ---------------- ln_prep: xhat_ff / xhat_bf / m planes (bf16 hi/lo) ----------------
#define LNPAD 132
extern "C" __global__ void __launch_bounds__(256) ln_prep_kernel(
    const float* __restrict__ front, const float* __restrict__ back) {
    extern __shared__ float sm[];
    float* xf = sm;
    float* xb = sm + 128 * LNPAD;
    __shared__ float s_mean[2][128], s_rstd[2][128];
    int T = blockIdx.x, g0 = T * 128, b = g0 >> 14, n0 = g0 & (NSEQ - 1);
    int tid = threadIdx.x;
    const float* fp = front + (size_t)b * 128 * NSEQ + n0;
    const float* bp = back  + (size_t)b * 128 * NSEQ + n0;
#pragma unroll
    for (int it = 0; it < 16; ++it) {
        int idx = tid + it * 256, d = idx >> 5, v = idx & 31;
        *(float4*)(xf + d * LNPAD + v * 4) = *(const float4*)(fp + (size_t)d * NSEQ + v * 4);
        *(float4*)(xb + d * LNPAD + v * 4) = *(const float4*)(bp + (size_t)d * NSEQ + v * 4);
    }
    __syncthreads();
    {
        int s = tid >> 7, t = tid & 127;
        const float* xp = s ? xb : xf;
        float a = 0.f, q = 0.f;
        for (int d = 0; d < 128; ++d) { float x = xp[d * LNPAD + t]; a += x; q += x * x; }
        float m = a * (1.f / 128.f);
        s_mean[s][t] = m;
        s_rstd[s][t] = rsqrtf(q * (1.f / 128.f) - m * m + 1e-5f);
    }
    __syncthreads();
    for (int it = 0; it < 24; ++it) {
        int idx = tid + it * 256;
        int p = idx >> 11, u = idx & 2047, tok = u & 127, kk = (u >> 7) * 8;
        float v[8];
        if (p < 2) {
            const float* xp = p ? xb : xf;
            float m = s_mean[p][tok], r = s_rstd[p][tok];
#pragma unroll
            for (int q = 0; q < 8; ++q) v[q] = (xp[(kk + q) * LNPAD + tok] - m) * r;
        } else {
#pragma unroll
            for (int q = 0; q < 8; ++q) v[q] = 0.5f * (xf[(kk + q) * LNPAD + tok] + xb[(kk + q) * LNPAD + tok]);
        }
        uint32_t hi[4], lo[4];
#pragma unroll
        for (int r = 0; r < 4; ++r) splt(v[2 * r], v[2 * r + 1], hi[r], lo[r]);
        size_t off = ((size_t)(T * 128 + tok)) * 128 + kk;
        *(uint4*)(&g_Abf[p][0][off]) = make_uint4(hi[0], hi[1], hi[2], hi[3]);
        *(uint4*)(&g_Abf[p][1][off]) = make_uint4(lo[0], lo[1], lo[2], lo[3]);
    }
}

// ---------------- gemm_in: 4 input GEMMs (u0,z0,u1,z1) ----------------
extern "C" __global__ void __launch_bounds__(256) gemm_in_kernel() {
    extern __shared__ unsigned char smu[];
    __shared__ float s_bias[128];
    int tid = threadIdx.x, warp = tid >> 5, lane = tid & 31;
    int T = blockIdx.x, cm = blockIdx.y;
    int ap = (cm == 1 || cm == 2) ? 1 : 0;
    float* dst = ((cm & 1) ? g_z : g_u) + ((cm >> 1) ? (size_t)BNTOK * 128 : 0);
    size_t abase = (size_t)T * 128 * 128;
    stage_plane(&g_Abf[ap][0][abase], smu, tid);
    stage_plane(&g_Abf[ap][1][abase], smu + 34816, tid);
    stage_plane(g_Wtb[cm][0], smu + 69632, tid);
    stage_plane(g_Wtb[cm][1], smu + 104448, tid);
    if (tid < 128) s_bias[tid] = g_biasv[cm * 128 + tid];
    __syncthreads();
    float acc[16][4];
#pragma unroll
    for (int n = 0; n < 16; ++n)
#pragma unroll
        for (int q = 0; q < 4; ++q) acc[n][q] = 0.f;
    gemm_compute(smu, acc, warp, lane);
    int r0 = warp * 16 + (lane >> 2);
    int cb = (lane & 3) * 2;
    float* d0 = dst + ((size_t)(T * 128) + r0) * 128;
#pragma unroll
    for (int nt = 0; nt < 16; ++nt) {
        int col = nt * 8 + cb;
        float b0 = s_bias[col], b1 = s_bias[col + 1];
        *(float2*)(d0 + col)            = make_float2(acc[nt][0] + b0, acc[nt][1] + b1);
        *(float2*)(d0 + 8 * 128 + col)  = make_float2(acc[nt][2] + b0, acc[nt][3] + b1);
    }
}

// ---------------- conv + SiLU ----------------
extern "C" __global__ void __launch_bounds__(256) conv_silu_kernel(
    const float* __restrict__ conv_w, const float* __restrict__ conv_b) {
    unsigned idx = blockIdx.x * 256u + threadIdx.x;
    int d = idx & 127, n = (idx >> 7) & (NSEQ - 1), i = idx >> 23;
    const float* w = conv_w + i * 512 + d * 4;
    float acc = conv_b[i * 128 + d];
#pragma unroll
    for (int k = 0; k < 4; ++k)
        if (n + k >= 3) acc += w[k] * g_u[idx + (unsigned)((k - 3) * 128)];
    g_uc[idx] = acc * sigmoidf_fast(acc);
}

// ---------------- proj: x_dbl -> dt/B/C ----------------
extern "C" __global__ void __launch_bounds__(128) proj_kernel(
    const float* __restrict__ Wxproj, const float* __restrict__ Wdt,
    const float* __restrict__ bdt) {
    __shared__ float ucs[32 * 132], wxp[128 * 24], xd[32 * 25], wdts[8 * 128], bdts[128];
    int i = blockIdx.y, g0 = blockIdx.x * 32, tid = threadIdx.x;
#pragma unroll
    for (int k = 0; k < 8; ++k) {
        int idx = tid + k * 128, t = idx >> 5, dv = idx & 31;
        *(float4*)(ucs + t * 132 + dv * 4) =
            *(const float4*)(g_uc + ((size_t)i * BNTOK + g0 + t) * 128 + dv * 4);
    }
#pragma unroll
    for (int k = 0; k < 24; ++k) wxp[tid + k * 128] = Wxproj[i * 3072 + tid + k * 128];
#pragma unroll
    for (int k = 0; k < 8; ++k) wdts[tid + k * 128] = Wdt[i * 1024 + tid + k * 128];
    bdts[tid] = bdt[i * 128 + tid];
    __syncthreads();
    {
        int t = tid >> 2, p = tid & 3, j0 = p * 6;
        float a[6];
#pragma unroll
        for (int q = 0; q < 6; ++q) a[q] = 0.f;
        for (int d = 0; d < 128; ++d) {
            float x = ucs[t * 132 + d];
#pragma unroll
            for (int q = 0; q < 6; ++q) a[q] += x * wxp[d * 24 + j0 + q];
        }
#pragma unroll
        for (int q = 0; q < 6; ++q) xd[t * 25 + j0 + q] = a[q];
    }
    __syncthreads();
    for (int t = 0; t < 32; ++t) {
        float acc = bdts[tid];
#pragma unroll
        for (int r = 0; r < 8; ++r) acc += xd[t * 25 + r] * wdts[r * 128 + tid];
        g_dt[((size_t)i * BNTOK + g0 + t) * 128 + tid] = softplusf(acc);
    }
    for (int idx = tid; idx < 512; idx += 128) {
        int t = idx >> 4, q = idx & 15;
        float v = xd[t * 25 + 8 + q];
        size_t gg = ((size_t)i * BNTOK + g0 + t) * 8;
        if (q < 8) g_B[gg + q] = v; else g_C[gg + q - 8] = v;
    }
}

// ---------------- scan A/B/C ----------------
extern "C" __global__ void __launch_bounds__(128) scan_a_kernel(const float* __restrict__ A_log) {
    __shared__ float Bs[LC * 8];
    int bx = blockIdx.x, c = bx & (NCH - 1), b = (bx >> 8) & 3, i = bx >> 10, d = threadIdx.x;
    float a[8];
#pragma unroll
    for (int s = 0; s < 8; ++s) a[s] = -__expf(A_log[i * 1024 + d * 8 + s]);
    size_t g0 = (size_t)i * BNTOK + b * NSEQ + c * LC;
    for (int k = d; k < LC * 8; k += 128) Bs[k] = g_B[g0 * 8 + k];
    __syncthreads();
    float P[8], h[8];
#pragma unroll
    for (int s = 0; s < 8; ++s) { P[s] = 1.f; h[s] = 0.f; }
    const float* dtp = g_dt + g0 * 128 + d;
    const float* ucp = g_uc + g0 * 128 + d;
#pragma unroll 2
    for (int t = 0; t < LC; ++t) {
        float dtv = dtp[t * 128], du = dtv * ucp[t * 128];
#pragma unroll
        for (int s = 0; s < 8; ++s) {
            float dA = __expf(dtv * a[s]);
            P[s] *= dA;
            h[s] = dA * h[s] + du * Bs[t * 8 + s];
        }
    }
    size_t o = ((size_t)((i * 4 + b) * NCH + c)) * 1024 + d * 8;
    *(float4*)(g_P + o) = make_float4(P[0], P[1], P[2], P[3]);
    *(float4*)(g_P + o + 4) = make_float4(P[4], P[5], P[6], P[7]);
    *(float4*)(g_Q + o) = make_float4(h[0], h[1], h[2], h[3]);
    *(float4*)(g_Q + o + 4) = make_float4(h[4], h[5], h[6], h[7]);
}

extern "C" __global__ void __launch_bounds__(256) scan_b_kernel() {
    int idx = blockIdx.x * 256 + threadIdx.x;
    int ib = idx >> 10, ds = idx & 1023;
    size_t base = (size_t)ib * NCH * 1024 + ds;
    float h = 0.f;
    for (int c0 = 0; c0 < NCH; c0 += 8) {
        float P8[8], Q8[8];
#pragma unroll
        for (int k = 0; k < 8; ++k) {
            size_t o = base + (size_t)(c0 + k) * 1024;
            P8[k] = g_P[o]; Q8[k] = g_Q[o];
        }
#pragma unroll
        for (int k = 0; k < 8; ++k) {
            size_t o = base + (size_t)(c0 + k) * 1024;
            g_H[o] = h;
            h = P8[k] * h + Q8[k];
        }
    }
}

extern "C" __global__ void __launch_bounds__(128) scan_c_kernel(
    const float* __restrict__ A_log, const float* __restrict__ Dp) {
    __shared__ float Bs[LC * 8], Cs[LC * 8];
    __shared__ float ys_s[LC * 131];
    int bx = blockIdx.x, c = bx & (NCH - 1), b = (bx >> 8) & 3, i = bx >> 10, d = threadIdx.x;
    float a[8];
#pragma unroll
    for (int s = 0; s < 8; ++s) a[s] = -__expf(A_log[i * 1024 + d * 8 + s]);
    float dp = Dp[i * 128 + d];
    size_t g0 = (size_t)i * BNTOK + b * NSEQ + c * LC;
    for (int k = d; k < LC * 8; k += 128) { Bs[k] = g_B[g0 * 8 + k]; Cs[k] = g_C[g0 * 8 + k]; }
    __syncthreads();
    size_t o = ((size_t)((i * 4 + b) * NCH + c)) * 1024 + d * 8;
    float h[8];
    float4 h0 = *(const float4*)(g_H + o), h1 = *(const float4*)(g_H + o + 4);
    h[0] = h0.x; h[1] = h0.y; h[2] = h0.z; h[3] = h0.w;
    h[4] = h1.x; h[5] = h1.y; h[6] = h1.z; h[7] = h1.w;
    const float* dtp = g_dt + g0 * 128 + d;
    const float* ucp = g_uc + g0 * 128 + d;
    const float* zp  = g_z  + g0 * 128 + d;
#pragma unroll 2
    for (int t = 0; t < LC; ++t) {
        float dtv = dtp[t * 128], ucv = ucp[t * 128], zv = zp[t * 128];
        float du = dtv * ucv, y = 0.f;
#pragma unroll
        for (int s = 0; s < 8; ++s) {
            float dA = __expf(dtv * a[s]);
            h[s] = dA * h[s] + du * Bs[t * 8 + s];
            y += h[s] * Cs[t * 8 + s];
        }
        ys_s[t * 131 + d] = (y + dp * ucv) * (zv * sigmoidf_fast(zv));
    }
    __syncthreads();
    int tile = (b * NSEQ + c * LC) >> 7;
    int half = (c & 1) * 64;
#pragma unroll
    for (int it = 0; it < 8; ++it) {
        int u = d + it * 128;
        int tt = u & 63, kk = (u >> 6) * 8;
        uint32_t hi[4], lo[4];
#pragma unroll
        for (int r = 0; r < 4; ++r)
            splt(ys_s[tt * 131 + kk + 2 * r], ys_s[tt * 131 + kk + 2 * r + 1], hi[r], lo[r]);
        size_t off = ((size_t)(tile * 128 + half + tt)) * 128 + kk;
        *(uint4*)(&g_Abf[3 + i][0][off]) = make_uint4(hi[0], hi[1], hi[2], hi[3]);
        *(uint4*)(&g_Abf[3 + i][1][off]) = make_uint4(lo[0], lo[1], lo[2], lo[3]);
    }
}

// ---------------- gemm_out: 3 accumulated phases + channel-major store ----------------
extern "C" __global__ void __launch_bounds__(256) gemm_out_kernel(float* __restrict__ outp) {
    extern __shared__ unsigned char smu[];
    int tid = threadIdx.x, warp = tid >> 5, lane = tid & 31;
    int T = blockIdx.x;
    float acc[16][4];
#pragma unroll
    for (int n = 0; n < 16; ++n)
#pragma unroll
        for (int q = 0; q < 4; ++q) acc[n][q] = 0.f;
    size_t abase = (size_t)T * 128 * 128;
    for (int p = 0; p < 3; ++p) {
        __syncthreads();
        stage_plane(&g_Abf[2 + p][0][abase], smu, tid);
        stage_plane(&g_Abf[2 + p][1][abase], smu + 34816, tid);
        stage_plane(g_Wtb[4 + p][0], smu + 69632, tid);
        stage_plane(g_Wtb[4 + p][1], smu + 104448, tid);
        __syncthreads();
        gemm_compute(smu, acc, warp, lane);
    }
    __syncthreads();
    // bounce through smem for coalesced channel-major store
    float* res = (float*)smu;   // 128 x 132
    int r0 = warp * 16 + (lane >> 2);
    int cb = (lane & 3) * 2;
#pragma unroll
    for (int nt = 0; nt < 16; ++nt) {
        int col = nt * 8 + cb;
        res[r0 * 132 + col]           = acc[nt][0];
        res[r0 * 132 + col + 1]       = acc[nt][1];
        res[(r0 + 8) * 132 + col]     = acc[nt][2];
        res[(r0 + 8) * 132 + col + 1] = acc[nt][3];
    }
    __syncthreads();
    int g0 = T * 128, b = g0 >> 14, n0 = g0 & (NSEQ - 1);
    int j = tid >> 1, t0 = (tid & 1) * 64;
    float bias = g_biasv[512 + j];
    float* ob = outp + ((size_t)b * 128 + j) * NSEQ + n0 + t0;
#pragma unroll
    for (int t = 0; t < 64; t += 4) {
        float4 v;
        v.x = res[(t0 + t + 0) * 132 + j] + bias;
        v.y = res[(t0 + t + 1) * 132 + j] + bias;
        v.z = res[(t0 + t + 2) * 132 + j] + bias;
        v.w = res[(t0 + t + 3) * 132 + j] + bias;
        *(float4*)(ob + t) = v;
    }
}

// ---------------- launch ----------------
extern "C" void kernel_launch(void* const* d_in, const int* in_sizes, int n_in,
                              void* d_out, int out_size) {
    const float* front  = (const float*)d_in[0];
    const float* back   = (const float*)d_in[1];
    const float* ln0w   = (const float*)d_in[2];
    const float* ln0b   = (const float*)d_in[3];
    const float* ln1w   = (const float*)d_in[4];
    const float* ln1b   = (const float*)d_in[5];
    const float* Wx     = (const float*)d_in[6];
    const float* Wz     = (const float*)d_in[7];
    const float* conv_w = (const float*)d_in[8];
    const float* conv_b = (const float*)d_in[9];
    const float* Wxproj = (const float*)d_in[10];
    const float* Wdt    = (const float*)d_in[11];
    const float* bdt    = (const float*)d_in[12];
    const float* A_log  = (const float*)d_in[13];
    const float* Dp     = (const float*)d_in[14];
    const float* Wout_m = (const float*)d_in[15];
    const float* bout_m = (const float*)d_in[16];
    const float* Wout   = (const float*)d_in[17];
    const float* bout   = (const float*)d_in[18];
    float* out = (float*)d_out;

    const int SM_LN  = 2 * 128 * LNPAD * 4;
    const int SM_MMA = 139264;
    cudaFuncSetAttribute(ln_prep_kernel, cudaFuncAttributeMaxDynamicSharedMemorySize, SM_LN);
    cudaFuncSetAttribute(gemm_in_kernel, cudaFuncAttributeMaxDynamicSharedMemorySize, SM_MMA);
    cudaFuncSetAttribute(gemm_out_kernel, cudaFuncAttributeMaxDynamicSharedMemorySize, SM_MMA);

    prep_w_kernel<<<dim3(128, 7), 128>>>(ln0w, ln0b, ln1w, ln1b, Wx, Wz, Wout_m, bout_m, Wout, bout);
    ln_prep_kernel<<<NTILE, 256, SM_LN>>>(front, back);
    gemm_in_kernel<<<dim3(NTILE, 4), 256, SM_MMA>>>();
    conv_silu_kernel<<<65536, 256>>>(conv_w, conv_b);
    proj_kernel<<<dim3(2048, 2), 128>>>(Wxproj, Wdt, bdt);
    scan_a_kernel<<<2048, 128>>>(A_log);
    scan_b_kernel<<<32, 256>>>();
    scan_c_kernel<<<2048, 128>>>(A_log, Dp);
    gemm_out_kernel<<<NTILE, 256, SM_MMA>>>(out);
}

// round 6
// speedup vs baseline: 1.5122x; 1.0838x over previous
#include <cuda_runtime.h>
#include <cuda_bf16.h>
#include <cstdint>

#define NSEQ   16384
#define BNTOK  65536
#define LC     64
#define NCH    256
#define NTILE  512
#define SASTR  272   // smem row stride in bytes (136 bf16)

// A planes: 0=xhat_ff 1=xhat_bf 2=m 3=y0 4=y1 ; [hi/lo] ; row-major [token][128]
__device__ __nv_bfloat16 g_Abf[5][2][(size_t)BNTOK * 128];
// W planes transposed [j][k]: 0..3 = u0,z0,u1,z1 ; 4=Wout ; 5=Weff0 ; 6=Weff1
__device__ __nv_bfloat16 g_Wtb[7][2][16384];
__device__ float g_biasv[640];

__device__ float g_z   [2u*BNTOK*128];
__device__ float g_uc  [2u*BNTOK*128];
__device__ float g_xdbl[2u*BNTOK*24];
__device__ float g_P [2u*4*NCH*128*8];
__device__ float g_Q [2u*4*NCH*128*8];
__device__ float g_H [2u*4*NCH*128*8];

__device__ __forceinline__ float sigmoidf_fast(float x) { return 1.0f / (1.0f + __expf(-x)); }
__device__ __forceinline__ float softplusf(float x) { return (x > 15.0f) ? x : __logf(1.0f + __expf(x)); }
__device__ __forceinline__ uint32_t su32(const void* p) { return (uint32_t)__cvta_generic_to_shared(p); }

__device__ __forceinline__ void splt(float a, float b, uint32_t& hi, uint32_t& lo) {
    __nv_bfloat162 h, l;
    h.x = __float2bfloat16_rn(a); h.y = __float2bfloat16_rn(b);
    l.x = __float2bfloat16_rn(a - __bfloat162float(h.x));
    l.y = __float2bfloat16_rn(b - __bfloat162float(h.y));
    hi = *(uint32_t*)&h; lo = *(uint32_t*)&l;
}
__device__ __forceinline__ void ldsm4(uint32_t addr, uint32_t r[4]) {
    asm volatile("ldmatrix.sync.aligned.m8n8.x4.shared.b16 {%0,%1,%2,%3}, [%4];"
                 : "=r"(r[0]), "=r"(r[1]), "=r"(r[2]), "=r"(r[3]) : "r"(addr));
}
__device__ __forceinline__ void mma16816(float d[4], const uint32_t a[4], const uint32_t b[2]) {
    asm volatile("mma.sync.aligned.m16n8k16.row.col.f32.bf16.bf16.f32 "
                 "{%0,%1,%2,%3},{%4,%5,%6,%7},{%8,%9},{%0,%1,%2,%3};"
                 : "+f"(d[0]), "+f"(d[1]), "+f"(d[2]), "+f"(d[3])
                 : "r"(a[0]), "r"(a[1]), "r"(a[2]), "r"(a[3]), "r"(b[0]), "r"(b[1]));
}

__device__ __forceinline__ void stage_plane(const __nv_bfloat16* __restrict__ g,
                                            unsigned char* s, int tid) {
#pragma unroll
    for (int it = 0; it < 8; ++it) {
        int idx = tid + it * 256;
        int r = idx >> 4, c = idx & 15;
        *(uint4*)(s + r * SASTR + c * 16) = ((const uint4*)g)[idx];
    }
}

// 3-pass hi/lo split 128x128x128 GEMM: Ah@0, Al@34816, Bh@69632, Bl@104448
__device__ __forceinline__ void gemm_compute(unsigned char* smem, float acc[16][4],
                                             int warp, int lane) {
    uint32_t sb = su32(smem);
    int row = lane & 7, g = lane >> 3;
    uint32_t aoff = (uint32_t)((warp * 16 + (g & 1) * 8 + row) * SASTR + (g >> 1) * 16);
    uint32_t boff = (uint32_t)(((g >> 1) * 8 + row) * SASTR + (g & 1) * 16);
#pragma unroll
    for (int pass = 0; pass < 3; ++pass) {
        uint32_t Ab = sb + (pass == 1 ? 34816u : 0u);
        uint32_t Bb = sb + 69632u + (pass == 2 ? 34816u : 0u);
#pragma unroll
        for (int kk = 0; kk < 8; ++kk) {
            uint32_t k2 = (uint32_t)kk * 32u;
            uint32_t a[4];
            ldsm4(Ab + aoff + k2, a);
#pragma unroll
            for (int nt = 0; nt < 8; ++nt) {
                uint32_t br[4];
                ldsm4(Bb + boff + (uint32_t)(nt * 16 * SASTR) + k2, br);
                mma16816(acc[2 * nt], a, br);
                mma16816(acc[2 * nt + 1], a, br + 2);
            }
        }
    }
}

// ---------------- prep_w ----------------
extern "C" __global__ void prep_w_kernel(
    const float* __restrict__ ln0w, const float* __restrict__ ln0b,
    const float* __restrict__ ln1w, const float* __restrict__ ln1b,
    const float* __restrict__ Wx, const float* __restrict__ Wz,
    const float* __restrict__ Wm, const float* __restrict__ bm,
    const float* __restrict__ Wout, const float* __restrict__ bout) {
    int j = blockIdx.x, pl = blockIdx.y, k = threadIdx.x;
    __shared__ float red[128];
    float v = 0.f, bc = 0.f;
    if (pl < 4) {
        int dir = pl >> 1;
        const float* W  = ((pl & 1) ? Wz : Wx) + dir * 16384;
        const float* lw = ((pl & 1) ? ln1w : ln0w) + dir * 128;
        const float* lb = ((pl & 1) ? ln1b : ln0b) + dir * 128;
        float wv = W[k * 128 + j];
        v = lw[k] * wv; bc = lb[k] * wv;
    } else if (pl == 4) {
        float wv = Wout[k * 128 + j];
        v = wv; bc = 0.5f * (bm[k] + bm[128 + k]) * wv;
    } else {
        int i = pl - 5;
        float acc = 0.f;
        for (int t = 0; t < 128; ++t) acc += Wm[i * 16384 + k * 128 + t] * Wout[t * 128 + j];
        v = 0.5f * acc;
    }
    __nv_bfloat16 h = __float2bfloat16_rn(v);
    g_Wtb[pl][0][j * 128 + k] = h;
    g_Wtb[pl][1][j * 128 + k] = __float2bfloat16_rn(v - __bfloat162float(h));
    if (pl < 5) {
        red[k] = bc; __syncthreads();
        if (k == 0) {
            float s = 0.f;
            for (int t = 0; t < 128; ++t) s += red[t];
            if (pl < 4) g_biasv[pl * 128 + j] = s;
            else        g_biasv[512 + j] = s + bout[j];
        }
    }
}

// ---------------- ln_prep ----------------
#define LNPAD 132
extern "C" __global__ void __launch_bounds__(256) ln_prep_kernel(
    const float* __restrict__ front, const float* __restrict__ back) {
    extern __shared__ float sm[];
    float* xf = sm;
    float* xb = sm + 128 * LNPAD;
    __shared__ float s_mean[2][128], s_rstd[2][128];
    int T = blockIdx.x, g0 = T * 128, b = g0 >> 14, n0 = g0 & (NSEQ - 1);
    int tid = threadIdx.x;
    const float* fp = front + (size_t)b * 128 * NSEQ + n0;
    const float* bp = back  + (size_t)b * 128 * NSEQ + n0;
#pragma unroll
    for (int it = 0; it < 16; ++it) {
        int idx = tid + it * 256, d = idx >> 5, v = idx & 31;
        *(float4*)(xf + d * LNPAD + v * 4) = *(const float4*)(fp + (size_t)d * NSEQ + v * 4);
        *(float4*)(xb + d * LNPAD + v * 4) = *(const float4*)(bp + (size_t)d * NSEQ + v * 4);
    }
    __syncthreads();
    {
        int s = tid >> 7, t = tid & 127;
        const float* xp = s ? xb : xf;
        float a = 0.f, q = 0.f;
        for (int d = 0; d < 128; ++d) { float x = xp[d * LNPAD + t]; a += x; q += x * x; }
        float m = a * (1.f / 128.f);
        s_mean[s][t] = m;
        s_rstd[s][t] = rsqrtf(q * (1.f / 128.f) - m * m + 1e-5f);
    }
    __syncthreads();
    for (int it = 0; it < 24; ++it) {
        int idx = tid + it * 256;
        int p = idx >> 11, u = idx & 2047, tok = u & 127, kk = (u >> 7) * 8;
        float v[8];
        if (p < 2) {
            const float* xp = p ? xb : xf;
            float m = s_mean[p][tok], r = s_rstd[p][tok];
#pragma unroll
            for (int q = 0; q < 8; ++q) v[q] = (xp[(kk + q) * LNPAD + tok] - m) * r;
        } else {
#pragma unroll
            for (int q = 0; q < 8; ++q) v[q] = 0.5f * (xf[(kk + q) * LNPAD + tok] + xb[(kk + q) * LNPAD + tok]);
        }
        uint32_t hi[4], lo[4];
#pragma unroll
        for (int r = 0; r < 4; ++r) splt(v[2 * r], v[2 * r + 1], hi[r], lo[r]);
        size_t off = ((size_t)(T * 128 + tok)) * 128 + kk;
        *(uint4*)(&g_Abf[p][0][off]) = make_uint4(hi[0], hi[1], hi[2], hi[3]);
        *(uint4*)(&g_Abf[p][1][off]) = make_uint4(lo[0], lo[1], lo[2], lo[3]);
    }
}

// ---------------- gemm_in: u-combos get conv+silu+proj epilogue; z-combos plain ----------------
extern "C" __global__ void __launch_bounds__(256) gemm_in_kernel(
    const float* __restrict__ conv_w, const float* __restrict__ conv_b,
    const float* __restrict__ Wxproj) {
    extern __shared__ unsigned char smu[];
    __shared__ float s_bias[128];
    __shared__ float s_uh[3 * 128];
    __shared__ float s_cw[128 * 4];
    __shared__ float s_cb[128];
    __shared__ float s_wxp[128 * 24];
    int tid = threadIdx.x, warp = tid >> 5, lane = tid & 31;
    int T = blockIdx.x, cm = blockIdx.y;
    int ap = (cm == 1 || cm == 2) ? 1 : 0;
    int dir = cm >> 1;
    bool is_u = (cm & 1) == 0;

    size_t abase = (size_t)T * 128 * 128;
    stage_plane(&g_Abf[ap][0][abase], smu, tid);
    stage_plane(&g_Abf[ap][1][abase], smu + 34816, tid);
    stage_plane(g_Wtb[cm][0], smu + 69632, tid);
    stage_plane(g_Wtb[cm][1], smu + 104448, tid);
    if (tid < 128) s_bias[tid] = g_biasv[cm * 128 + tid];
    if (is_u) {
        if (tid < 128) {
            *(float4*)(s_cw + tid * 4) = *(const float4*)(conv_w + dir * 512 + tid * 4);
            s_cb[tid] = conv_b[dir * 128 + tid];
        }
#pragma unroll
        for (int it = 0; it < 12; ++it)
            s_wxp[tid + it * 256] = Wxproj[dir * 3072 + tid + it * 256];
    }
    __syncthreads();

    float acc[16][4];
#pragma unroll
    for (int n = 0; n < 16; ++n)
#pragma unroll
        for (int q = 0; q < 4; ++q) acc[n][q] = 0.f;
    gemm_compute(smu, acc, warp, lane);

    int r0 = warp * 16 + (lane >> 2);
    int cb2 = (lane & 3) * 2;

    if (!is_u) {
        float* dst = g_z + (size_t)dir * BNTOK * 128;
        float* d0 = dst + ((size_t)(T * 128) + r0) * 128;
#pragma unroll
        for (int nt = 0; nt < 16; ++nt) {
            int col = nt * 8 + cb2;
            float b0 = s_bias[col], b1 = s_bias[col + 1];
            *(float2*)(d0 + col)           = make_float2(acc[nt][0] + b0, acc[nt][1] + b1);
            *(float2*)(d0 + 8 * 128 + col) = make_float2(acc[nt][2] + b0, acc[nt][3] + b1);
        }
        return;
    }

    // ---- u path ----
    __syncthreads();                    // done reading Ah/Al
    float* ut = (float*)smu;            // 128 x 132 fp32 u tile (overwrites Ah/Al)
#pragma unroll
    for (int nt = 0; nt < 16; ++nt) {
        int col = nt * 8 + cb2;
        float b0 = s_bias[col], b1 = s_bias[col + 1];
        ut[r0 * 132 + col]           = acc[nt][0] + b0;
        ut[r0 * 132 + col + 1]       = acc[nt][1] + b1;
        ut[(r0 + 8) * 132 + col]     = acc[nt][2] + b0;
        ut[(r0 + 8) * 132 + col + 1] = acc[nt][3] + b1;
    }
    // halo: u for global tokens T*128-3 .. T*128-1 (zero at sequence start)
    if (tid < 128) {
        int j = tid;
        if ((T & 127) == 0) {
            s_uh[j] = 0.f; s_uh[128 + j] = 0.f; s_uh[256 + j] = 0.f;
        } else {
            const __nv_bfloat16* ah = &g_Abf[ap][0][((size_t)(T * 128) - 3) * 128];
            const __nv_bfloat16* al = &g_Abf[ap][1][((size_t)(T * 128) - 3) * 128];
            const __nv_bfloat16* wh = (const __nv_bfloat16*)(smu + 69632 + j * SASTR);
            const __nv_bfloat16* wl = (const __nv_bfloat16*)(smu + 104448 + j * SASTR);
            float a0 = s_bias[j], a1 = s_bias[j], a2 = s_bias[j];
            for (int k = 0; k < 128; ++k) {
                float w = __bfloat162float(wh[k]) + __bfloat162float(wl[k]);
                a0 += w * (__bfloat162float(ah[k])       + __bfloat162float(al[k]));
                a1 += w * (__bfloat162float(ah[128 + k]) + __bfloat162float(al[128 + k]));
                a2 += w * (__bfloat162float(ah[256 + k]) + __bfloat162float(al[256 + k]));
            }
            s_uh[j] = a0; s_uh[128 + j] = a1; s_uh[256 + j] = a2;
        }
    }
    __syncthreads();
    // conv(k=4) + silu -> uc (global + smem tile at 69632)
    float* uct = (float*)(smu + 69632);
    float* ucg = g_uc + (size_t)dir * BNTOK * 128 + (size_t)T * 128 * 128;
#pragma unroll
    for (int it = 0; it < 16; ++it) {
        int idx = tid + it * 256;          // 4096 units: t x (32 d-quads)
        int t = idx >> 5, dq = (idx & 31) * 4;
        float4 r3, r2, r1, r0v;
        r0v = *(float4*)(ut + t * 132 + dq);
        if (t >= 3) {
            r3 = *(float4*)(ut + (t - 3) * 132 + dq);
            r2 = *(float4*)(ut + (t - 2) * 132 + dq);
            r1 = *(float4*)(ut + (t - 1) * 132 + dq);
        } else {
            r3 = (t - 3 + 3 < 3) ? *(float4*)(s_uh + (t) * 128 + dq)     : *(float4*)(ut + (t - 3) * 132 + dq);
            r2 = (t - 2 < 0)     ? *(float4*)(s_uh + (t + 1) * 128 + dq) : *(float4*)(ut + (t - 2) * 132 + dq);
            r1 = (t - 1 < 0)     ? *(float4*)(s_uh + (t + 2) * 128 + dq) : *(float4*)(ut + (t - 1) * 132 + dq);
        }
        float4 o;
        float* w;
        w = s_cw + (dq + 0) * 4;
        o.x = s_cb[dq + 0] + w[0] * r3.x + w[1] * r2.x + w[2] * r1.x + w[3] * r0v.x;
        w = s_cw + (dq + 1) * 4;
        o.y = s_cb[dq + 1] + w[0] * r3.y + w[1] * r2.y + w[2] * r1.y + w[3] * r0v.y;
        w = s_cw + (dq + 2) * 4;
        o.z = s_cb[dq + 2] + w[0] * r3.z + w[1] * r2.z + w[2] * r1.z + w[3] * r0v.z;
        w = s_cw + (dq + 3) * 4;
        o.w = s_cb[dq + 3] + w[0] * r3.w + w[1] * r2.w + w[2] * r1.w + w[3] * r0v.w;
        o.x *= sigmoidf_fast(o.x); o.y *= sigmoidf_fast(o.y);
        o.z *= sigmoidf_fast(o.z); o.w *= sigmoidf_fast(o.w);
        *(float4*)(uct + t * 132 + dq) = o;
        *(float4*)(ucg + (size_t)t * 128 + dq) = o;
    }
    __syncthreads();
    // proj: x_dbl = uc @ Wxproj (24 cols); 2 threads per token
    {
        int tok = tid >> 1, hf = tid & 1;
        float a[12];
#pragma unroll
        for (int q = 0; q < 12; ++q) a[q] = 0.f;
        const float* ur = uct + tok * 132;
        const float* wp = s_wxp + hf * 12;
        for (int d = 0; d < 128; ++d) {
            float uv = ur[d];
#pragma unroll
            for (int q = 0; q < 12; ++q) a[q] += uv * wp[d * 24 + q];
        }
        float* xo = g_xdbl + ((size_t)dir * BNTOK + T * 128 + tok) * 24 + hf * 12;
        *(float4*)(xo + 0) = make_float4(a[0], a[1], a[2], a[3]);
        *(float4*)(xo + 4) = make_float4(a[4], a[5], a[6], a[7]);
        *(float4*)(xo + 8) = make_float4(a[8], a[9], a[10], a[11]);
    }
}

// ---------------- scan A/B/C ----------------
extern "C" __global__ void __launch_bounds__(128) scan_a_kernel(
    const float* __restrict__ A_log, const float* __restrict__ Wdt,
    const float* __restrict__ bdt) {
    __shared__ float xds[LC * 24];
    __shared__ float wdts[8 * 128], bdts[128];
    int bx = blockIdx.x, c = bx & (NCH - 1), b = (bx >> 8) & 3, i = bx >> 10, d = threadIdx.x;
    float a[8];
#pragma unroll
    for (int s = 0; s < 8; ++s) a[s] = -__expf(A_log[i * 1024 + d * 8 + s]);
    size_t g0 = (size_t)i * BNTOK + b * NSEQ + c * LC;
#pragma unroll
    for (int k = 0; k < 12; ++k) xds[d + k * 128] = g_xdbl[g0 * 24 + d + k * 128];
#pragma unroll
    for (int k = 0; k < 8; ++k) wdts[d + k * 128] = Wdt[i * 1024 + d + k * 128];
    bdts[d] = bdt[i * 128 + d];
    __syncthreads();
    float P[8], h[8];
#pragma unroll
    for (int s = 0; s < 8; ++s) { P[s] = 1.f; h[s] = 0.f; }
    const float* ucp = g_uc + g0 * 128 + d;
#pragma unroll 2
    for (int t = 0; t < LC; ++t) {
        float dtacc = bdts[d];
#pragma unroll
        for (int r = 0; r < 8; ++r) dtacc += xds[t * 24 + r] * wdts[r * 128 + d];
        float dtv = softplusf(dtacc);
        float du = dtv * ucp[t * 128];
#pragma unroll
        for (int s = 0; s < 8; ++s) {
            float dA = __expf(dtv * a[s]);
            P[s] *= dA;
            h[s] = dA * h[s] + du * xds[t * 24 + 8 + s];
        }
    }
    size_t o = ((size_t)((i * 4 + b) * NCH + c)) * 1024 + d * 8;
    *(float4*)(g_P + o) = make_float4(P[0], P[1], P[2], P[3]);
    *(float4*)(g_P + o + 4) = make_float4(P[4], P[5], P[6], P[7]);
    *(float4*)(g_Q + o) = make_float4(h[0], h[1], h[2], h[3]);
    *(float4*)(g_Q + o + 4) = make_float4(h[4], h[5], h[6], h[7]);
}

extern "C" __global__ void __launch_bounds__(256) scan_b_kernel() {
    int idx = blockIdx.x * 256 + threadIdx.x;
    int ib = idx >> 10, ds = idx & 1023;
    size_t base = (size_t)ib * NCH * 1024 + ds;
    float h = 0.f;
    for (int c0 = 0; c0 < NCH; c0 += 8) {
        float P8[8], Q8[8];
#pragma unroll
        for (int k = 0; k < 8; ++k) {
            size_t o = base + (size_t)(c0 + k) * 1024;
            P8[k] = g_P[o]; Q8[k] = g_Q[o];
        }
#pragma unroll
        for (int k = 0; k < 8; ++k) {
            size_t o = base + (size_t)(c0 + k) * 1024;
            g_H[o] = h;
            h = P8[k] * h + Q8[k];
        }
    }
}

extern "C" __global__ void __launch_bounds__(128) scan_c_kernel(
    const float* __restrict__ A_log, const float* __restrict__ Dp,
    const float* __restrict__ Wdt, const float* __restrict__ bdt) {
    __shared__ float xds[LC * 24];
    __shared__ float wdts[8 * 128], bdts[128];
    __shared__ float ys_s[LC * 131];
    int bx = blockIdx.x, c = bx & (NCH - 1), b = (bx >> 8) & 3, i = bx >> 10, d = threadIdx.x;
    float a[8];
#pragma unroll
    for (int s = 0; s < 8; ++s) a[s] = -__expf(A_log[i * 1024 + d * 8 + s]);
    float dp = Dp[i * 128 + d];
    size_t g0 = (size_t)i * BNTOK + b * NSEQ + c * LC;
#pragma unroll
    for (int k = 0; k < 12; ++k) xds[d + k * 128] = g_xdbl[g0 * 24 + d + k * 128];
#pragma unroll
    for (int k = 0; k < 8; ++k) wdts[d + k * 128] = Wdt[i * 1024 + d + k * 128];
    bdts[d] = bdt[i * 128 + d];
    __syncthreads();
    size_t o = ((size_t)((i * 4 + b) * NCH + c)) * 1024 + d * 8;
    float h[8];
    float4 h0 = *(const float4*)(g_H + o), h1 = *(const float4*)(g_H + o + 4);
    h[0] = h0.x; h[1] = h0.y; h[2] = h0.z; h[3] = h0.w;
    h[4] = h1.x; h[5] = h1.y; h[6] = h1.z; h[7] = h1.w;
    const float* ucp = g_uc + g0 * 128 + d;
    const float* zp  = g_z  + g0 * 128 + d;
#pragma unroll 2
    for (int t = 0; t < LC; ++t) {
        float dtacc = bdts[d];
#pragma unroll
        for (int r = 0; r < 8; ++r) dtacc += xds[t * 24 + r] * wdts[r * 128 + d];
        float dtv = softplusf(dtacc);
        float ucv = ucp[t * 128], zv = zp[t * 128];
        float du = dtv * ucv, y = 0.f;
#pragma unroll
        for (int s = 0; s < 8; ++s) {
            float dA = __expf(dtv * a[s]);
            h[s] = dA * h[s] + du * xds[t * 24 + 8 + s];
            y += h[s] * xds[t * 24 + 16 + s];
        }
        ys_s[t * 131 + d] = (y + dp * ucv) * (zv * sigmoidf_fast(zv));
    }
    __syncthreads();
    int tile = (b * NSEQ + c * LC) >> 7;
    int half = (c & 1) * 64;
#pragma unroll
    for (int it = 0; it < 8; ++it) {
        int u = d + it * 128;
        int tt = u & 63, kk = (u >> 6) * 8;
        uint32_t hi[4], lo[4];
#pragma unroll
        for (int r = 0; r < 4; ++r)
            splt(ys_s[tt * 131 + kk + 2 * r], ys_s[tt * 131 + kk + 2 * r + 1], hi[r], lo[r]);
        size_t off = ((size_t)(tile * 128 + half + tt)) * 128 + kk;
        *(uint4*)(&g_Abf[3 + i][0][off]) = make_uint4(hi[0], hi[1], hi[2], hi[3]);
        *(uint4*)(&g_Abf[3 + i][1][off]) = make_uint4(lo[0], lo[1], lo[2], lo[3]);
    }
}

// ---------------- gemm_out ----------------
extern "C" __global__ void __launch_bounds__(256) gemm_out_kernel(float* __restrict__ outp) {
    extern __shared__ unsigned char smu[];
    int tid = threadIdx.x, warp = tid >> 5, lane = tid & 31;
    int T = blockIdx.x;
    float acc[16][4];
#pragma unroll
    for (int n = 0; n < 16; ++n)
#pragma unroll
        for (int q = 0; q < 4; ++q) acc[n][q] = 0.f;
    size_t abase = (size_t)T * 128 * 128;
    for (int p = 0; p < 3; ++p) {
        __syncthreads();
        stage_plane(&g_Abf[2 + p][0][abase], smu, tid);
        stage_plane(&g_Abf[2 + p][1][abase], smu + 34816, tid);
        stage_plane(g_Wtb[4 + p][0], smu + 69632, tid);
        stage_plane(g_Wtb[4 + p][1], smu + 104448, tid);
        __syncthreads();
        gemm_compute(smu, acc, warp, lane);
    }
    __syncthreads();
    float* res = (float*)smu;
    int r0 = warp * 16 + (lane >> 2);
    int cb = (lane & 3) * 2;
#pragma unroll
    for (int nt = 0; nt < 16; ++nt) {
        int col = nt * 8 + cb;
        res[r0 * 132 + col]           = acc[nt][0];
        res[r0 * 132 + col + 1]       = acc[nt][1];
        res[(r0 + 8) * 132 + col]     = acc[nt][2];
        res[(r0 + 8) * 132 + col + 1] = acc[nt][3];
    }
    __syncthreads();
    int g0 = T * 128, b = g0 >> 14, n0 = g0 & (NSEQ - 1);
    int j = tid >> 1, t0 = (tid & 1) * 64;
    float bias = g_biasv[512 + j];
    float* ob = outp + ((size_t)b * 128 + j) * NSEQ + n0 + t0;
#pragma unroll
    for (int t = 0; t < 64; t += 4) {
        float4 v;
        v.x = res[(t0 + t + 0) * 132 + j] + bias;
        v.y = res[(t0 + t + 1) * 132 + j] + bias;
        v.z = res[(t0 + t + 2) * 132 + j] + bias;
        v.w = res[(t0 + t + 3) * 132 + j] + bias;
        *(float4*)(ob + t) = v;
    }
}

// ---------------- launch ----------------
extern "C" void kernel_launch(void* const* d_in, const int* in_sizes, int n_in,
                              void* d_out, int out_size) {
    const float* front  = (const float*)d_in[0];
    const float* back   = (const float*)d_in[1];
    const float* ln0w   = (const float*)d_in[2];
    const float* ln0b   = (const float*)d_in[3];
    const float* ln1w   = (const float*)d_in[4];
    const float* ln1b   = (const float*)d_in[5];
    const float* Wx     = (const float*)d_in[6];
    const float* Wz     = (const float*)d_in[7];
    const float* conv_w = (const float*)d_in[8];
    const float* conv_b = (const float*)d_in[9];
    const float* Wxproj = (const float*)d_in[10];
    const float* Wdt    = (const float*)d_in[11];
    const float* bdt    = (const float*)d_in[12];
    const float* A_log  = (const float*)d_in[13];
    const float* Dp     = (const float*)d_in[14];
    const float* Wout_m = (const float*)d_in[15];
    const float* bout_m = (const float*)d_in[16];
    const float* Wout   = (const float*)d_in[17];
    const float* bout   = (const float*)d_in[18];
    float* out = (float*)d_out;

    const int SM_LN  = 2 * 128 * LNPAD * 4;
    const int SM_MMA = 139264;
    cudaFuncSetAttribute(ln_prep_kernel, cudaFuncAttributeMaxDynamicSharedMemorySize, SM_LN);
    cudaFuncSetAttribute(gemm_in_kernel, cudaFuncAttributeMaxDynamicSharedMemorySize, SM_MMA);
    cudaFuncSetAttribute(gemm_out_kernel, cudaFuncAttributeMaxDynamicSharedMemorySize, SM_MMA);

    prep_w_kernel<<<dim3(128, 7), 128>>>(ln0w, ln0b, ln1w, ln1b, Wx, Wz, Wout_m, bout_m, Wout, bout);
    ln_prep_kernel<<<NTILE, 256, SM_LN>>>(front, back);
    gemm_in_kernel<<<dim3(NTILE, 4), 256, SM_MMA>>>(conv_w, conv_b, Wxproj);
    scan_a_kernel<<<2048, 128>>>(A_log, Wdt, bdt);
    scan_b_kernel<<<32, 256>>>();
    scan_c_kernel<<<2048, 128>>>(A_log, Dp, Wdt, bdt);
    gemm_out_kernel<<<NTILE, 256, SM_MMA>>>(out);
}